// round 2
// baseline (speedup 1.0000x reference)
#include <cuda_runtime.h>
#include <math.h>

#define N_ROWS 32768
#define IN_DIM 768
#define HID 2048
#define OUT_DIM 256
#define KCODES 1024

// ---------------- scratch (device globals: allocation-free) ----------------
__device__ float g_h[(size_t)N_ROWS * HID];        // 256 MB hidden (enc & dec reuse)
__device__ float g_scores[(size_t)N_ROWS * KCODES];// 128 MB score matrix
__device__ float g_decin[(size_t)N_ROWS * OUT_DIM];// 32 MB zq1+zq2+zq3
__device__ float g_emb2[KCODES];                   // per-code squared norms
__device__ float g_rownorm[N_ROWS];                // per-row ||ze||^2

// ---------------- fp32 SGEMM ----------------
// A: M x K row-major. BTRANS=false: B is K x Ncol row-major (C = act(A@B + bias)).
//                     BTRANS=true:  B is Ncol x K row-major; SCORE epilogue:
//                        C = fl( fl(rowterm[row] + bias[col]) - 2*acc )
// ACT: 0 none, 1 relu, 2 sigmoid.
template<int ACT, bool BTRANS>
__global__ void __launch_bounds__(256) sgemm_kernel(
    const float* __restrict__ A, const float* __restrict__ B,
    const float* __restrict__ bias, const float* __restrict__ rowterm,
    float* __restrict__ C,
    int M, int Ncol, int Kdim)
{
    __shared__ float As[16][128];
    __shared__ float Bs[16][128];

    const int bm = blockIdx.y;
    const int bn = blockIdx.x;
    const int tid = threadIdx.x;
    const int tx = tid & 15;      // 0..15 -> column group
    const int ty = tid >> 4;      // 0..15 -> row group

    const float* Ablk = A + (size_t)bm * 128 * Kdim;

    float acc[8][8];
    #pragma unroll
    for (int i = 0; i < 8; i++)
        #pragma unroll
        for (int j = 0; j < 8; j++) acc[i][j] = 0.0f;

    for (int kt = 0; kt < Kdim; kt += 16) {
        // --- load A tile (128 rows x 16 k), store transposed As[k][row]
        #pragma unroll
        for (int r = 0; r < 2; r++) {
            int L = tid + r * 256;          // 0..511 float4 loads
            int row = L >> 2;
            int k4 = (L & 3) * 4;
            float4 v = *reinterpret_cast<const float4*>(
                Ablk + (size_t)row * Kdim + kt + k4);
            As[k4 + 0][row] = v.x;
            As[k4 + 1][row] = v.y;
            As[k4 + 2][row] = v.z;
            As[k4 + 3][row] = v.w;
        }
        if (!BTRANS) {
            // B[k][m] tile: 16 x 128, coalesced along m
            #pragma unroll
            for (int r = 0; r < 2; r++) {
                int L = tid + r * 256;
                int kk = L >> 5;            // 0..15
                int m4 = (L & 31) * 4;
                float4 v = *reinterpret_cast<const float4*>(
                    B + (size_t)(kt + kk) * Ncol + (size_t)bn * 128 + m4);
                *reinterpret_cast<float4*>(&Bs[kk][m4]) = v;
            }
        } else {
            // B[code][c] tile: 128 codes x 16 c, scatter to Bs[c][code]
            #pragma unroll
            for (int r = 0; r < 2; r++) {
                int L = tid + r * 256;
                int code = L >> 2;
                int c4 = (L & 3) * 4;
                float4 v = *reinterpret_cast<const float4*>(
                    B + (size_t)(bn * 128 + code) * Kdim + kt + c4);
                Bs[c4 + 0][code] = v.x;
                Bs[c4 + 1][code] = v.y;
                Bs[c4 + 2][code] = v.z;
                Bs[c4 + 3][code] = v.w;
            }
        }
        __syncthreads();

        #pragma unroll
        for (int kk = 0; kk < 16; kk++) {
            float4 a0 = *reinterpret_cast<const float4*>(&As[kk][ty * 8]);
            float4 a1 = *reinterpret_cast<const float4*>(&As[kk][ty * 8 + 4]);
            float4 b0 = *reinterpret_cast<const float4*>(&Bs[kk][tx * 8]);
            float4 b1 = *reinterpret_cast<const float4*>(&Bs[kk][tx * 8 + 4]);
            float a[8] = {a0.x, a0.y, a0.z, a0.w, a1.x, a1.y, a1.z, a1.w};
            float b[8] = {b0.x, b0.y, b0.z, b0.w, b1.x, b1.y, b1.z, b1.w};
            #pragma unroll
            for (int i = 0; i < 8; i++)
                #pragma unroll
                for (int j = 0; j < 8; j++)
                    acc[i][j] = fmaf(a[i], b[j], acc[i][j]);
        }
        __syncthreads();
    }

    const int row0 = bm * 128 + ty * 8;
    const int col0 = bn * 128 + tx * 8;
    #pragma unroll
    for (int i = 0; i < 8; i++) {
        float* crow = C + (size_t)(row0 + i) * Ncol + col0;
        float rt = BTRANS ? rowterm[row0 + i] : 0.0f;
        #pragma unroll
        for (int j = 0; j < 8; j++) {
            float v;
            if (BTRANS) {
                // replicate reference rounding: t = fl(s1 + s2); d = fl(t - 2m)
                float t = __fadd_rn(rt, bias[col0 + j]);
                v = __fmaf_rn(-2.0f, acc[i][j], t);
            } else {
                v = acc[i][j] + bias[col0 + j];
                if (ACT == 1) v = fmaxf(v, 0.0f);
                if (ACT == 2) v = 1.0f / (1.0f + expf(-v));
            }
            crow[j] = v;
        }
    }
}

// ---------------- per-code squared norms ----------------
__global__ void __launch_bounds__(256) emb2_kernel(
    const float* __restrict__ emb, float* __restrict__ out)
{
    int warp = (blockIdx.x * 256 + threadIdx.x) >> 5;
    int lane = threadIdx.x & 31;
    if (warp >= KCODES) return;
    const float* e = emb + (size_t)warp * OUT_DIM;
    float s = 0.0f;
    #pragma unroll
    for (int c = lane; c < OUT_DIM; c += 32) s = fmaf(e[c], e[c], s);
    #pragma unroll
    for (int off = 16; off; off >>= 1)
        s += __shfl_down_sync(0xffffffffu, s, off);
    if (lane == 0) out[warp] = s;
}

// ---------------- per-row squared norms (one warp / row) ----------------
__global__ void __launch_bounds__(256) rownorm_kernel(
    const float* __restrict__ z, float* __restrict__ out, int nrows)
{
    int row = (blockIdx.x * 256 + threadIdx.x) >> 5;
    int lane = threadIdx.x & 31;
    if (row >= nrows) return;
    const float* zr = z + (size_t)row * OUT_DIM;
    float s = 0.0f;
    #pragma unroll
    for (int c = lane; c < OUT_DIM; c += 32) s = fmaf(zr[c], zr[c], s);
    #pragma unroll
    for (int off = 16; off; off >>= 1)
        s += __shfl_down_sync(0xffffffffu, s, off);
    if (lane == 0) out[row] = s;
}

// ---------------- argmin over scores + gather zq + residual (+ next rownorm) --
// Tie-break: lowest index (matches jnp.argmin first-occurrence).
__global__ void __launch_bounds__(256) argmin_kernel(
    const float* __restrict__ scores, const float* __restrict__ ze,
    const float* __restrict__ emb,
    float* __restrict__ n_out, float* __restrict__ zq_out,
    float* __restrict__ zenext_out, float* __restrict__ rownorm_out)
{
    int row = (blockIdx.x * 256 + threadIdx.x) >> 5;
    int lane = threadIdx.x & 31;
    if (row >= N_ROWS) return;

    const float* s = scores + (size_t)row * KCODES;
    float best = s[lane];
    int bidx = lane;
    #pragma unroll 8
    for (int i = lane + 32; i < KCODES; i += 32) {
        float v = s[i];
        if (v < best) { best = v; bidx = i; }   // strict < keeps first occurrence
    }
    #pragma unroll
    for (int off = 16; off; off >>= 1) {
        float v2 = __shfl_down_sync(0xffffffffu, best, off);
        int i2 = __shfl_down_sync(0xffffffffu, bidx, off);
        if (v2 < best || (v2 == best && i2 < bidx)) { best = v2; bidx = i2; }
    }
    bidx = __shfl_sync(0xffffffffu, bidx, 0);
    if (lane == 0) n_out[row] = (float)bidx;

    const float* e = emb + (size_t)bidx * OUT_DIM;
    const float* z = ze + (size_t)row * OUT_DIM;
    float* zq = zq_out + (size_t)row * OUT_DIM;
    if (zenext_out) {
        float* zn = zenext_out + (size_t)row * OUT_DIM;
        float nrm = 0.0f;
        #pragma unroll
        for (int c = lane; c < OUT_DIM; c += 32) {
            float ev = e[c];
            float r = z[c] - ev;
            zq[c] = ev;
            zn[c] = r;
            nrm = fmaf(r, r, nrm);
        }
        #pragma unroll
        for (int off = 16; off; off >>= 1)
            nrm += __shfl_down_sync(0xffffffffu, nrm, off);
        if (lane == 0) rownorm_out[row] = nrm;
    } else {
        #pragma unroll
        for (int c = lane; c < OUT_DIM; c += 32) zq[c] = e[c];
    }
}

// ---------------- dec_in = zq1 + zq2 + zq3 ----------------
__global__ void __launch_bounds__(256) add3_kernel(
    const float* __restrict__ a, const float* __restrict__ b,
    const float* __restrict__ c, float* __restrict__ o, int n)
{
    int i = blockIdx.x * 256 + threadIdx.x;
    if (i < n) o[i] = a[i] + b[i] + c[i];
}

// ---------------- launch ----------------
extern "C" void kernel_launch(void* const* d_in, const int* in_sizes, int n_in,
                              void* d_out, int out_size)
{
    const float* x    = (const float*)d_in[0];
    const float* We1  = (const float*)d_in[1];
    const float* be1  = (const float*)d_in[2];
    const float* We2  = (const float*)d_in[3];
    const float* be2  = (const float*)d_in[4];
    const float* Wd1  = (const float*)d_in[5];
    const float* bd1  = (const float*)d_in[6];
    const float* Wd2  = (const float*)d_in[7];
    const float* bd2  = (const float*)d_in[8];
    const float* emb1 = (const float*)d_in[9];
    const float* emb2c= (const float*)d_in[10];
    const float* emb3c= (const float*)d_in[11];

    float* out = (float*)d_out;
    // output layout: recon, ze1, ze2, ze3, zq1, zq2, zq3, n1, n2, n3 (all f32)
    float* recon = out;
    float* ze1 = recon + (size_t)N_ROWS * IN_DIM;
    float* ze2 = ze1 + (size_t)N_ROWS * OUT_DIM;
    float* ze3 = ze2 + (size_t)N_ROWS * OUT_DIM;
    float* zq1 = ze3 + (size_t)N_ROWS * OUT_DIM;
    float* zq2 = zq1 + (size_t)N_ROWS * OUT_DIM;
    float* zq3 = zq2 + (size_t)N_ROWS * OUT_DIM;
    float* n1  = zq3 + (size_t)N_ROWS * OUT_DIM;
    float* n2  = n1 + N_ROWS;
    float* n3  = n2 + N_ROWS;

    float *h, *sc, *decin, *e2, *rn;
    cudaGetSymbolAddress((void**)&h, g_h);
    cudaGetSymbolAddress((void**)&sc, g_scores);
    cudaGetSymbolAddress((void**)&decin, g_decin);
    cudaGetSymbolAddress((void**)&e2, g_emb2);
    cudaGetSymbolAddress((void**)&rn, g_rownorm);

    const dim3 blk(256);

    // ---- encoder ----
    sgemm_kernel<1, false><<<dim3(HID / 128, N_ROWS / 128), blk>>>(
        x, We1, be1, nullptr, h, N_ROWS, HID, IN_DIM);
    sgemm_kernel<0, false><<<dim3(OUT_DIM / 128, N_ROWS / 128), blk>>>(
        h, We2, be2, nullptr, ze1, N_ROWS, OUT_DIM, HID);

    // ---- quantize stage 1 ----
    rownorm_kernel<<<N_ROWS / 8, blk>>>(ze1, rn, N_ROWS);
    emb2_kernel<<<KCODES / 8, blk>>>(emb1, e2);
    sgemm_kernel<0, true><<<dim3(KCODES / 128, N_ROWS / 128), blk>>>(
        ze1, emb1, e2, rn, sc, N_ROWS, KCODES, OUT_DIM);
    argmin_kernel<<<N_ROWS / 8, blk>>>(sc, ze1, emb1, n1, zq1, ze2, rn);

    // ---- quantize stage 2 ----
    emb2_kernel<<<KCODES / 8, blk>>>(emb2c, e2);
    sgemm_kernel<0, true><<<dim3(KCODES / 128, N_ROWS / 128), blk>>>(
        ze2, emb2c, e2, rn, sc, N_ROWS, KCODES, OUT_DIM);
    argmin_kernel<<<N_ROWS / 8, blk>>>(sc, ze2, emb2c, n2, zq2, ze3, rn);

    // ---- quantize stage 3 (residual not an output) ----
    emb2_kernel<<<KCODES / 8, blk>>>(emb3c, e2);
    sgemm_kernel<0, true><<<dim3(KCODES / 128, N_ROWS / 128), blk>>>(
        ze3, emb3c, e2, rn, sc, N_ROWS, KCODES, OUT_DIM);
    argmin_kernel<<<N_ROWS / 8, blk>>>(sc, ze3, emb3c, n3, zq3, nullptr, nullptr);

    // ---- decoder ----
    add3_kernel<<<(N_ROWS * OUT_DIM) / 256, blk>>>(
        zq1, zq2, zq3, decin, N_ROWS * OUT_DIM);
    sgemm_kernel<2, false><<<dim3(HID / 128, N_ROWS / 128), blk>>>(
        decin, Wd1, bd1, nullptr, h, N_ROWS, HID, OUT_DIM);
    sgemm_kernel<0, false><<<dim3(IN_DIM / 128, N_ROWS / 128), blk>>>(
        h, Wd2, bd2, nullptr, recon, N_ROWS, IN_DIM, HID);
}

// round 3
// speedup vs baseline: 1.0000x; 1.0000x over previous
#include <cuda_runtime.h>
#include <math.h>

#define N_ROWS 32768
#define IN_DIM 768
#define HID 2048
#define OUT_DIM 256
#define KCODES 1024

// ---------------- scratch (device globals: allocation-free) ----------------
__device__ float g_h[(size_t)N_ROWS * HID];        // 256 MB hidden (enc & dec reuse)
__device__ float g_scores[(size_t)N_ROWS * KCODES];// 128 MB score matrix
__device__ float g_decin[(size_t)N_ROWS * OUT_DIM];// 32 MB zq1+zq2+zq3
__device__ float g_emb2[KCODES];                   // per-code squared norms
__device__ float g_rownorm[N_ROWS];                // per-row ||ze||^2

// ---------------- fp32 SGEMM ----------------
// A: M x K row-major. BTRANS=false: B is K x Ncol row-major (C = act(A@B + bias)).
//                     BTRANS=true:  B is Ncol x K row-major; SCORE epilogue:
//                        C = fl( fl(rowterm[row] + bias[col]) - 2*acc )
// ACT: 0 none, 1 relu, 2 sigmoid.
template<int ACT, bool BTRANS>
__global__ void __launch_bounds__(256) sgemm_kernel(
    const float* __restrict__ A, const float* __restrict__ B,
    const float* __restrict__ bias, const float* __restrict__ rowterm,
    float* __restrict__ C,
    int M, int Ncol, int Kdim)
{
    __shared__ float As[16][128];
    __shared__ float Bs[16][128];

    const int bm = blockIdx.y;
    const int bn = blockIdx.x;
    const int tid = threadIdx.x;
    const int tx = tid & 15;      // 0..15 -> column group
    const int ty = tid >> 4;      // 0..15 -> row group

    const float* Ablk = A + (size_t)bm * 128 * Kdim;

    float acc[8][8];
    #pragma unroll
    for (int i = 0; i < 8; i++)
        #pragma unroll
        for (int j = 0; j < 8; j++) acc[i][j] = 0.0f;

    for (int kt = 0; kt < Kdim; kt += 16) {
        // --- load A tile (128 rows x 16 k), store transposed As[k][row]
        #pragma unroll
        for (int r = 0; r < 2; r++) {
            int L = tid + r * 256;          // 0..511 float4 loads
            int row = L >> 2;
            int k4 = (L & 3) * 4;
            float4 v = *reinterpret_cast<const float4*>(
                Ablk + (size_t)row * Kdim + kt + k4);
            As[k4 + 0][row] = v.x;
            As[k4 + 1][row] = v.y;
            As[k4 + 2][row] = v.z;
            As[k4 + 3][row] = v.w;
        }
        if (!BTRANS) {
            // B[k][m] tile: 16 x 128, coalesced along m
            #pragma unroll
            for (int r = 0; r < 2; r++) {
                int L = tid + r * 256;
                int kk = L >> 5;            // 0..15
                int m4 = (L & 31) * 4;
                float4 v = *reinterpret_cast<const float4*>(
                    B + (size_t)(kt + kk) * Ncol + (size_t)bn * 128 + m4);
                *reinterpret_cast<float4*>(&Bs[kk][m4]) = v;
            }
        } else {
            // B[code][c] tile: 128 codes x 16 c, scatter to Bs[c][code]
            #pragma unroll
            for (int r = 0; r < 2; r++) {
                int L = tid + r * 256;
                int code = L >> 2;
                int c4 = (L & 3) * 4;
                float4 v = *reinterpret_cast<const float4*>(
                    B + (size_t)(bn * 128 + code) * Kdim + kt + c4);
                Bs[c4 + 0][code] = v.x;
                Bs[c4 + 1][code] = v.y;
                Bs[c4 + 2][code] = v.z;
                Bs[c4 + 3][code] = v.w;
            }
        }
        __syncthreads();

        #pragma unroll
        for (int kk = 0; kk < 16; kk++) {
            float4 a0 = *reinterpret_cast<const float4*>(&As[kk][ty * 8]);
            float4 a1 = *reinterpret_cast<const float4*>(&As[kk][ty * 8 + 4]);
            float4 b0 = *reinterpret_cast<const float4*>(&Bs[kk][tx * 8]);
            float4 b1 = *reinterpret_cast<const float4*>(&Bs[kk][tx * 8 + 4]);
            float a[8] = {a0.x, a0.y, a0.z, a0.w, a1.x, a1.y, a1.z, a1.w};
            float b[8] = {b0.x, b0.y, b0.z, b0.w, b1.x, b1.y, b1.z, b1.w};
            #pragma unroll
            for (int i = 0; i < 8; i++)
                #pragma unroll
                for (int j = 0; j < 8; j++)
                    acc[i][j] = fmaf(a[i], b[j], acc[i][j]);
        }
        __syncthreads();
    }

    const int row0 = bm * 128 + ty * 8;
    const int col0 = bn * 128 + tx * 8;
    #pragma unroll
    for (int i = 0; i < 8; i++) {
        float* crow = C + (size_t)(row0 + i) * Ncol + col0;
        float rt = BTRANS ? rowterm[row0 + i] : 0.0f;
        #pragma unroll
        for (int j = 0; j < 8; j++) {
            float v;
            if (BTRANS) {
                // replicate reference rounding: t = fl(s1 + s2); d = fl(t - 2m)
                float t = __fadd_rn(rt, bias[col0 + j]);
                v = __fmaf_rn(-2.0f, acc[i][j], t);
            } else {
                v = acc[i][j] + bias[col0 + j];
                if (ACT == 1) v = fmaxf(v, 0.0f);
                if (ACT == 2) v = 1.0f / (1.0f + expf(-v));
            }
            crow[j] = v;
        }
    }
}

// ---------------- per-code squared norms ----------------
__global__ void __launch_bounds__(256) emb2_kernel(
    const float* __restrict__ emb, float* __restrict__ out)
{
    int warp = (blockIdx.x * 256 + threadIdx.x) >> 5;
    int lane = threadIdx.x & 31;
    if (warp >= KCODES) return;
    const float* e = emb + (size_t)warp * OUT_DIM;
    float s = 0.0f;
    #pragma unroll
    for (int c = lane; c < OUT_DIM; c += 32) s = fmaf(e[c], e[c], s);
    #pragma unroll
    for (int off = 16; off; off >>= 1)
        s += __shfl_down_sync(0xffffffffu, s, off);
    if (lane == 0) out[warp] = s;
}

// ---------------- per-row squared norms (one warp / row) ----------------
__global__ void __launch_bounds__(256) rownorm_kernel(
    const float* __restrict__ z, float* __restrict__ out, int nrows)
{
    int row = (blockIdx.x * 256 + threadIdx.x) >> 5;
    int lane = threadIdx.x & 31;
    if (row >= nrows) return;
    const float* zr = z + (size_t)row * OUT_DIM;
    float s = 0.0f;
    #pragma unroll
    for (int c = lane; c < OUT_DIM; c += 32) s = fmaf(zr[c], zr[c], s);
    #pragma unroll
    for (int off = 16; off; off >>= 1)
        s += __shfl_down_sync(0xffffffffu, s, off);
    if (lane == 0) out[row] = s;
}

// ---------------- argmin over scores + gather zq + residual (+ next rownorm) --
// Tie-break: lowest index (matches jnp.argmin first-occurrence).
__global__ void __launch_bounds__(256) argmin_kernel(
    const float* __restrict__ scores, const float* __restrict__ ze,
    const float* __restrict__ emb,
    float* __restrict__ n_out, float* __restrict__ zq_out,
    float* __restrict__ zenext_out, float* __restrict__ rownorm_out)
{
    int row = (blockIdx.x * 256 + threadIdx.x) >> 5;
    int lane = threadIdx.x & 31;
    if (row >= N_ROWS) return;

    const float* s = scores + (size_t)row * KCODES;
    float best = s[lane];
    int bidx = lane;
    #pragma unroll 8
    for (int i = lane + 32; i < KCODES; i += 32) {
        float v = s[i];
        if (v < best) { best = v; bidx = i; }   // strict < keeps first occurrence
    }
    #pragma unroll
    for (int off = 16; off; off >>= 1) {
        float v2 = __shfl_down_sync(0xffffffffu, best, off);
        int i2 = __shfl_down_sync(0xffffffffu, bidx, off);
        if (v2 < best || (v2 == best && i2 < bidx)) { best = v2; bidx = i2; }
    }
    bidx = __shfl_sync(0xffffffffu, bidx, 0);
    if (lane == 0) n_out[row] = (float)bidx;

    const float* e = emb + (size_t)bidx * OUT_DIM;
    const float* z = ze + (size_t)row * OUT_DIM;
    float* zq = zq_out + (size_t)row * OUT_DIM;
    if (zenext_out) {
        float* zn = zenext_out + (size_t)row * OUT_DIM;
        float nrm = 0.0f;
        #pragma unroll
        for (int c = lane; c < OUT_DIM; c += 32) {
            float ev = e[c];
            float r = z[c] - ev;
            zq[c] = ev;
            zn[c] = r;
            nrm = fmaf(r, r, nrm);
        }
        #pragma unroll
        for (int off = 16; off; off >>= 1)
            nrm += __shfl_down_sync(0xffffffffu, nrm, off);
        if (lane == 0) rownorm_out[row] = nrm;
    } else {
        #pragma unroll
        for (int c = lane; c < OUT_DIM; c += 32) zq[c] = e[c];
    }
}

// ---------------- dec_in = zq1 + zq2 + zq3 ----------------
__global__ void __launch_bounds__(256) add3_kernel(
    const float* __restrict__ a, const float* __restrict__ b,
    const float* __restrict__ c, float* __restrict__ o, int n)
{
    int i = blockIdx.x * 256 + threadIdx.x;
    if (i < n) o[i] = a[i] + b[i] + c[i];
}

// ---------------- launch ----------------
extern "C" void kernel_launch(void* const* d_in, const int* in_sizes, int n_in,
                              void* d_out, int out_size)
{
    const float* x    = (const float*)d_in[0];
    const float* We1  = (const float*)d_in[1];
    const float* be1  = (const float*)d_in[2];
    const float* We2  = (const float*)d_in[3];
    const float* be2  = (const float*)d_in[4];
    const float* Wd1  = (const float*)d_in[5];
    const float* bd1  = (const float*)d_in[6];
    const float* Wd2  = (const float*)d_in[7];
    const float* bd2  = (const float*)d_in[8];
    const float* emb1 = (const float*)d_in[9];
    const float* emb2c= (const float*)d_in[10];
    const float* emb3c= (const float*)d_in[11];

    float* out = (float*)d_out;
    // output layout: recon, ze1, ze2, ze3, zq1, zq2, zq3, n1, n2, n3 (all f32)
    float* recon = out;
    float* ze1 = recon + (size_t)N_ROWS * IN_DIM;
    float* ze2 = ze1 + (size_t)N_ROWS * OUT_DIM;
    float* ze3 = ze2 + (size_t)N_ROWS * OUT_DIM;
    float* zq1 = ze3 + (size_t)N_ROWS * OUT_DIM;
    float* zq2 = zq1 + (size_t)N_ROWS * OUT_DIM;
    float* zq3 = zq2 + (size_t)N_ROWS * OUT_DIM;
    float* n1  = zq3 + (size_t)N_ROWS * OUT_DIM;
    float* n2  = n1 + N_ROWS;
    float* n3  = n2 + N_ROWS;

    float *h, *sc, *decin, *e2, *rn;
    cudaGetSymbolAddress((void**)&h, g_h);
    cudaGetSymbolAddress((void**)&sc, g_scores);
    cudaGetSymbolAddress((void**)&decin, g_decin);
    cudaGetSymbolAddress((void**)&e2, g_emb2);
    cudaGetSymbolAddress((void**)&rn, g_rownorm);

    const dim3 blk(256);

    // ---- encoder ----
    sgemm_kernel<1, false><<<dim3(HID / 128, N_ROWS / 128), blk>>>(
        x, We1, be1, nullptr, h, N_ROWS, HID, IN_DIM);
    sgemm_kernel<0, false><<<dim3(OUT_DIM / 128, N_ROWS / 128), blk>>>(
        h, We2, be2, nullptr, ze1, N_ROWS, OUT_DIM, HID);

    // ---- quantize stage 1 ----
    rownorm_kernel<<<N_ROWS / 8, blk>>>(ze1, rn, N_ROWS);
    emb2_kernel<<<KCODES / 8, blk>>>(emb1, e2);
    sgemm_kernel<0, true><<<dim3(KCODES / 128, N_ROWS / 128), blk>>>(
        ze1, emb1, e2, rn, sc, N_ROWS, KCODES, OUT_DIM);
    argmin_kernel<<<N_ROWS / 8, blk>>>(sc, ze1, emb1, n1, zq1, ze2, rn);

    // ---- quantize stage 2 ----
    emb2_kernel<<<KCODES / 8, blk>>>(emb2c, e2);
    sgemm_kernel<0, true><<<dim3(KCODES / 128, N_ROWS / 128), blk>>>(
        ze2, emb2c, e2, rn, sc, N_ROWS, KCODES, OUT_DIM);
    argmin_kernel<<<N_ROWS / 8, blk>>>(sc, ze2, emb2c, n2, zq2, ze3, rn);

    // ---- quantize stage 3 (residual not an output) ----
    emb2_kernel<<<KCODES / 8, blk>>>(emb3c, e2);
    sgemm_kernel<0, true><<<dim3(KCODES / 128, N_ROWS / 128), blk>>>(
        ze3, emb3c, e2, rn, sc, N_ROWS, KCODES, OUT_DIM);
    argmin_kernel<<<N_ROWS / 8, blk>>>(sc, ze3, emb3c, n3, zq3, nullptr, nullptr);

    // ---- decoder ----
    add3_kernel<<<(N_ROWS * OUT_DIM) / 256, blk>>>(
        zq1, zq2, zq3, decin, N_ROWS * OUT_DIM);
    sgemm_kernel<2, false><<<dim3(HID / 128, N_ROWS / 128), blk>>>(
        decin, Wd1, bd1, nullptr, h, N_ROWS, HID, OUT_DIM);
    sgemm_kernel<0, false><<<dim3(IN_DIM / 128, N_ROWS / 128), blk>>>(
        h, Wd2, bd2, nullptr, recon, N_ROWS, IN_DIM, HID);
}